// round 6
// baseline (speedup 1.0000x reference)
#include <cuda_runtime.h>
#include <math.h>

// ---------------------------------------------------------------------------
// N=3072 all-pairs mask/bucket kernel.
// Out sections (float32, concatenated): dxyz (N,N,3), buckets (N,N),
// dscanid (N,N), mask (N,N).
//
// R3 -> R4: i-tiling (4 rows/block, j data held in registers, 4x fewer
// global load wavefronts), SIMD byte-packed meta compares (vabsdiffu4 +
// vcmpleu4), streaming stores.
// ---------------------------------------------------------------------------

#define MAXN 8192
__device__ float4   g_P[MAXN];   // {x, y, z, cb_as_float}
__device__ unsigned g_X[MAXN];   // xb

// cb bytes: b0=c0, b1=c1, b2=c2, b3=blk
// xb bytes: b0=xc0+16, b1=xc1+16, b2=batch, b3=0
__global__ void pack_kernel(const float* __restrict__ xyz,
                            const int*   __restrict__ grid, int N) {
    int i = blockIdx.x * blockDim.x + threadIdx.x;
    if (i >= N) return;
    float x = xyz[3*i+0], y = xyz[3*i+1], z = xyz[3*i+2];
    int batch = grid[5*i+0], blk = grid[5*i+1];
    int c0 = grid[5*i+2], c1 = grid[5*i+3], c2 = grid[5*i+4];
    // xy_coarse = ceil(xyz[:, :2] / 3.0)  — pinned IEEE division
    int xc0 = (int)ceilf(__fdiv_rn(x, 3.0f));
    int xc1 = (int)ceilf(__fdiv_rn(y, 3.0f));
    unsigned cb = (unsigned)(c0 & 0xFF)
                | ((unsigned)(c1 & 0xFF) << 8)
                | ((unsigned)(c2 & 0xFF) << 16)
                | ((unsigned)(blk & 0xFF) << 24);
    unsigned xb = (unsigned)((xc0 + 16) & 0xFF)
                | ((unsigned)((xc1 + 16) & 0xFF) << 8)
                | ((unsigned)(batch & 0xFF) << 16);
    g_P[i] = make_float4(x, y, z, __uint_as_float(cb));
    g_X[i] = xb;
}

// bucket_base without the +BETA offset: integer-valued float v, ref = BETA + v.
__device__ __forceinline__ float bucket_v(float d) {
    float x  = d * 2.0f;            // x / RES, RES = 0.5 (exact)
    float xa = fabsf(x);
    if (xa <= 2.0f) {
        return rintf(x);            // round-half-even == jnp.round
    } else {
        float lr  = logf(xa * 0.5f) * 0.48089834696298783f; // 1/ln(8)
        float sup = fminf(rintf(2.0f - 6.0f * lr), 8.0f);
        return (x > 0.0f) ? sup : -sup;
    }
}

#define TI 4

__global__ __launch_bounds__(256)
void pair_kernel(float* __restrict__ out, int N) {
    int j0 = (blockIdx.x * blockDim.x + threadIdx.x) * 4;
    int i0 = blockIdx.y * TI;
    if (j0 >= N) return;
    int nvalid = (N - j0 < 4) ? (N - j0) : 4;

    // Load 4 j-points once, reuse across TI rows.
    float4   pj[4];
    unsigned xbj[4];
#pragma unroll
    for (int t = 0; t < 4; t++) {
        int j = (t < nvalid) ? (j0 + t) : j0;
        pj[t]  = g_P[j];
        xbj[t] = g_X[j];
    }

    size_t NN = (size_t)N * (size_t)N;

#pragma unroll
    for (int ii = 0; ii < TI; ii++) {
        int i = i0 + ii;
        if (i >= N) break;

        float4   pi  = g_P[i];            // broadcast load (1 wavefront/warp)
        unsigned cbi = __float_as_uint(pi.w);
        unsigned xbi = g_X[i];
        int bi = (int)(cbi >> 24);
        int si = bi >> 1;

        float dxs[12];
        float bks[4], dss[4], mks[4];

#pragma unroll
        for (int t = 0; t < 4; t++) {
            if (t >= nvalid) {
                dxs[3*t] = dxs[3*t+1] = dxs[3*t+2] = 0.f;
                bks[t] = dss[t] = mks[t] = 0.f;
                continue;
            }
            unsigned cbj = __float_as_uint(pj[t].w);

            // forcekeep = coord_adj (3 bytes <=1) & blk equal (byte3 ==0)
            unsigned v1 = __vcmpleu4(__vabsdiffu4(cbi, cbj), 0x00010101u);
            bool forcekeep = (v1 == 0xFFFFFFFFu);

            // v2: bytes0,1 = coarse-adj, byte2 = batch-eq, byte3 trivially true
            unsigned v2 = __vcmpleu4(__vabsdiffu4(xbi, xbj[t]), 0x00000101u);
            bool kc_batch = (v2 == 0xFFFFFFFFu);          // batch_eq & keep_coarse
            bool batch_eq = (v2 & 0x00FF0000u) != 0u;

            int  bj       = (int)(cbj >> 24);
            bool block_le = (bi <= bj);

            float dx = pi.x - pj[t].x;
            float dy = pi.y - pj[t].y;
            float dz = pi.z - pj[t].z;
            bool keepr = (dx*dx + dy*dy + dz*dz) <= 9.0f;

            // mask = batch_eq & block_le & (fk | (kc & keepr))
            bool mask = block_le & ((forcekeep & batch_eq) | (kc_batch & keepr));

            dxs[3*t+0] = mask ? dx : 0.0f;
            dxs[3*t+1] = mask ? dy : 0.0f;
            dxs[3*t+2] = mask ? dz : 0.0f;

            int b = 0, ds = 0;
            if (mask) {
                b = 289 * (8 + (int)bucket_v(dx))
                  +  17 * (8 + (int)bucket_v(dy))
                  +        (8 + (int)bucket_v(dz));
                ds = (bj >> 1) - si;
            }
            bks[t] = (float)b;
            dss[t] = (float)ds;
            mks[t] = mask ? 1.0f : 0.0f;
        }

        size_t row = (size_t)i * (size_t)N + (size_t)j0;

        if (nvalid == 4) {
            float4* dp = reinterpret_cast<float4*>(out + row * 3);
            __stcs(dp + 0, make_float4(dxs[0], dxs[1], dxs[2],  dxs[3]));
            __stcs(dp + 1, make_float4(dxs[4], dxs[5], dxs[6],  dxs[7]));
            __stcs(dp + 2, make_float4(dxs[8], dxs[9], dxs[10], dxs[11]));
            __stcs(reinterpret_cast<float4*>(out + 3*NN + row),
                   make_float4(bks[0], bks[1], bks[2], bks[3]));
            __stcs(reinterpret_cast<float4*>(out + 4*NN + row),
                   make_float4(dss[0], dss[1], dss[2], dss[3]));
            __stcs(reinterpret_cast<float4*>(out + 5*NN + row),
                   make_float4(mks[0], mks[1], mks[2], mks[3]));
        } else {
            for (int t = 0; t < nvalid; t++) {
                out[(row + t)*3 + 0] = dxs[3*t+0];
                out[(row + t)*3 + 1] = dxs[3*t+1];
                out[(row + t)*3 + 2] = dxs[3*t+2];
                out[3*NN + row + t] = bks[t];
                out[4*NN + row + t] = dss[t];
                out[5*NN + row + t] = mks[t];
            }
        }
    }
}

extern "C" void kernel_launch(void* const* d_in, const int* in_sizes, int n_in,
                              void* d_out, int out_size) {
    const float* xyz  = (const float*)d_in[0];
    const int*   grid = (const int*)d_in[1];
    int N = in_sizes[0] / 3;
    float* out = (float*)d_out;

    pack_kernel<<<(N + 255) / 256, 256>>>(xyz, grid, N);

    dim3 g((N + 1023) / 1024, (N + TI - 1) / TI);
    pair_kernel<<<g, 256>>>(out, N);
}

// round 7
// speedup vs baseline: 1.0168x; 1.0168x over previous
#include <cuda_runtime.h>
#include <math.h>

// ---------------------------------------------------------------------------
// N=3072 all-pairs mask/bucket kernel.
// Out sections (float32, concatenated): dxyz (N,N,3), buckets (N,N),
// dscanid (N,N), mask (N,N).
//
// R6 -> R7: revert i-tiling (it cost occupancy: regs 40->58, occ 63->43%),
// keep SIMD byte-packed meta compares + streaming stores. One row per
// block-Y, 4 j per thread, TI=1.
// ---------------------------------------------------------------------------

#define MAXN 8192
__device__ float4   g_P[MAXN];   // {x, y, z, cb_as_float}
__device__ unsigned g_X[MAXN];   // xb

// cb bytes: b0=c0, b1=c1, b2=c2, b3=blk
// xb bytes: b0=xc0+16, b1=xc1+16, b2=batch, b3=0
__global__ void pack_kernel(const float* __restrict__ xyz,
                            const int*   __restrict__ grid, int N) {
    int i = blockIdx.x * blockDim.x + threadIdx.x;
    if (i >= N) return;
    float x = xyz[3*i+0], y = xyz[3*i+1], z = xyz[3*i+2];
    int batch = grid[5*i+0], blk = grid[5*i+1];
    int c0 = grid[5*i+2], c1 = grid[5*i+3], c2 = grid[5*i+4];
    // xy_coarse = ceil(xyz[:, :2] / 3.0)  — pinned IEEE division
    int xc0 = (int)ceilf(__fdiv_rn(x, 3.0f));
    int xc1 = (int)ceilf(__fdiv_rn(y, 3.0f));
    unsigned cb = (unsigned)(c0 & 0xFF)
                | ((unsigned)(c1 & 0xFF) << 8)
                | ((unsigned)(c2 & 0xFF) << 16)
                | ((unsigned)(blk & 0xFF) << 24);
    unsigned xb = (unsigned)((xc0 + 16) & 0xFF)
                | ((unsigned)((xc1 + 16) & 0xFF) << 8)
                | ((unsigned)(batch & 0xFF) << 16);
    g_P[i] = make_float4(x, y, z, __uint_as_float(cb));
    g_X[i] = xb;
}

// bucket_base without the +BETA offset: integer-valued float v, ref = BETA + v.
__device__ __forceinline__ float bucket_v(float d) {
    float x  = d * 2.0f;            // x / RES, RES = 0.5 (exact)
    float xa = fabsf(x);
    if (xa <= 2.0f) {
        return rintf(x);            // round-half-even == jnp.round
    } else {
        float lr  = logf(xa * 0.5f) * 0.48089834696298783f; // 1/ln(8)
        float sup = fminf(rintf(2.0f - 6.0f * lr), 8.0f);
        return (x > 0.0f) ? sup : -sup;
    }
}

__global__ __launch_bounds__(256)
void pair_kernel(float* __restrict__ out, int N) {
    int i  = blockIdx.y;
    int j0 = (blockIdx.x * blockDim.x + threadIdx.x) * 4;
    if (j0 >= N) return;
    int nvalid = (N - j0 < 4) ? (N - j0) : 4;

    float4   pi  = g_P[i];            // broadcast load
    unsigned cbi = __float_as_uint(pi.w);
    unsigned xbi = g_X[i];
    int bi = (int)(cbi >> 24);
    int si = bi >> 1;

    float dxs[12];
    float bks[4], dss[4], mks[4];

#pragma unroll
    for (int t = 0; t < 4; t++) {
        if (t >= nvalid) {
            dxs[3*t] = dxs[3*t+1] = dxs[3*t+2] = 0.f;
            bks[t] = dss[t] = mks[t] = 0.f;
            continue;
        }
        int j = j0 + t;
        float4   pj  = g_P[j];
        unsigned cbj = __float_as_uint(pj.w);
        unsigned xbj = g_X[j];

        // forcekeep = coord_adj (bytes0-2 absdiff<=1) & blk equal (byte3 diff==0)
        unsigned v1 = __vcmpleu4(__vabsdiffu4(cbi, cbj), 0x00010101u);
        bool forcekeep = (v1 == 0xFFFFFFFFu);

        // v2: bytes0,1 = coarse-adj, byte2 = batch-eq, byte3 trivially true
        unsigned v2 = __vcmpleu4(__vabsdiffu4(xbi, xbj), 0x00000101u);
        bool kc_batch = (v2 == 0xFFFFFFFFu);          // batch_eq & keep_coarse
        bool batch_eq = (v2 & 0x00FF0000u) != 0u;

        int  bj       = (int)(cbj >> 24);
        bool block_le = (bi <= bj);

        float dx = pi.x - pj.x;
        float dy = pi.y - pj.y;
        float dz = pi.z - pj.z;
        bool keepr = (dx*dx + dy*dy + dz*dz) <= 9.0f;

        // mask = batch_eq & block_le & (fk | (kc & keepr))
        bool mask = block_le & ((forcekeep & batch_eq) | (kc_batch & keepr));

        dxs[3*t+0] = mask ? dx : 0.0f;
        dxs[3*t+1] = mask ? dy : 0.0f;
        dxs[3*t+2] = mask ? dz : 0.0f;

        int b = 0, ds = 0;
        if (mask) {
            // MUL = [289, 17, 1]; exact integer arithmetic
            b = 289 * (8 + (int)bucket_v(dx))
              +  17 * (8 + (int)bucket_v(dy))
              +        (8 + (int)bucket_v(dz));
            ds = (bj >> 1) - si;
        }
        bks[t] = (float)b;
        dss[t] = (float)ds;
        mks[t] = mask ? 1.0f : 0.0f;
    }

    size_t NN  = (size_t)N * (size_t)N;
    size_t row = (size_t)i * (size_t)N + (size_t)j0;

    if (nvalid == 4) {
        float4* dp = reinterpret_cast<float4*>(out + row * 3);
        __stcs(dp + 0, make_float4(dxs[0], dxs[1], dxs[2],  dxs[3]));
        __stcs(dp + 1, make_float4(dxs[4], dxs[5], dxs[6],  dxs[7]));
        __stcs(dp + 2, make_float4(dxs[8], dxs[9], dxs[10], dxs[11]));
        __stcs(reinterpret_cast<float4*>(out + 3*NN + row),
               make_float4(bks[0], bks[1], bks[2], bks[3]));
        __stcs(reinterpret_cast<float4*>(out + 4*NN + row),
               make_float4(dss[0], dss[1], dss[2], dss[3]));
        __stcs(reinterpret_cast<float4*>(out + 5*NN + row),
               make_float4(mks[0], mks[1], mks[2], mks[3]));
    } else {
        for (int t = 0; t < nvalid; t++) {
            out[(row + t)*3 + 0] = dxs[3*t+0];
            out[(row + t)*3 + 1] = dxs[3*t+1];
            out[(row + t)*3 + 2] = dxs[3*t+2];
            out[3*NN + row + t] = bks[t];
            out[4*NN + row + t] = dss[t];
            out[5*NN + row + t] = mks[t];
        }
    }
}

extern "C" void kernel_launch(void* const* d_in, const int* in_sizes, int n_in,
                              void* d_out, int out_size) {
    const float* xyz  = (const float*)d_in[0];
    const int*   grid = (const int*)d_in[1];
    int N = in_sizes[0] / 3;
    float* out = (float*)d_out;

    pack_kernel<<<(N + 255) / 256, 256>>>(xyz, grid, N);

    dim3 g((N + 1023) / 1024, N);
    pair_kernel<<<g, 256>>>(out, N);
}